// round 14
// baseline (speedup 1.0000x reference)
#include <cuda_runtime.h>

#define Sdim 4096
#define WIN  256
#define Hn   16
#define TQ   64
#define CK   64
#define NT   256
#define KSTR 68
#define VSTR 68
#define PSTR 68

#define SM_KV 4096
#define SM_P  (SM_KV + 64*KSTR)          /* 8448 */
#define SMEM_FLOATS (SM_P + 64*PSTR)     /* 12800 floats = 51200 B */

typedef unsigned long long u64;

__device__ __forceinline__ u64 pk2(float v) {
    u64 r; asm("mov.b64 %0,{%1,%1};" : "=l"(r) : "f"(v)); return r;
}
__device__ __forceinline__ void fma2(u64 &d, u64 a, u64 b) {
    asm("fma.rn.f32x2 %0,%1,%2,%0;" : "+l"(d) : "l"(a), "l"(b));
}
__device__ __forceinline__ float2 upk2(u64 v) {
    float2 f; asm("mov.b64 {%0,%1},%2;" : "=f"(f.x), "=f"(f.y) : "l"(v)); return f;
}

__global__ __launch_bounds__(NT, 4)
void swa_kernel(const float* __restrict__ Q, const float* __restrict__ K,
                const float* __restrict__ V, float* __restrict__ outp,
                float* __restrict__ attn)
{
    extern __shared__ float sm[];
    float* Qs  = sm;                    // [64d][64q], pre-scaled 0.125
    float* KV  = sm + SM_KV;            // G1: K^T [64d][KSTR] swizzled; G2: V [64k][VSTR]
    float* Pst = sm + SM_P;             // G2: P [64q][PSTR]

    const int h    = blockIdx.y;
    const int qb   = blockIdx.x * TQ;
    const int tid  = threadIdx.x;
    const int koff = qb - WIN;          // band buffer keys [koff, koff+640)
    const int goff = koff >> 2;
    const int warp = tid >> 5, lane = tid & 31;
    float* abase = attn + (size_t)(h*Sdim + qb)*Sdim;

    const float4* Q4 = (const float4*)(Q + (size_t)(h*Sdim + qb)*64);
    const float4* K4 = (const float4*)(K + (size_t)h*Sdim*64);
    const float4* V4 = (const float4*)(V + (size_t)h*Sdim*64);

    // ---- Q load + transpose to d-major, fold in 1/8 ----
    #pragma unroll
    for (int i = 0; i < 4; i++) {
        int idx = tid + NT*i;
        int q = idx & 63, dg = idx >> 6;        // dg 0..15
        float4 v = Q4[q*16 + dg];
        Qs[(4*dg+0)*64 + q] = v.x * 0.125f;
        Qs[(4*dg+1)*64 + q] = v.y * 0.125f;
        Qs[(4*dg+2)*64 + q] = v.z * 0.125f;
        Qs[(4*dg+3)*64 + q] = v.w * 0.125f;
    }

    // ---- zero-fill attn outside band: warp owns rows 8w..8w+7 ----
    {
        int lo = goff > 0 ? goff : 0;
        int hi = goff + 160 < 1024 ? goff + 160 : 1024;
        const float4 z = make_float4(0.f,0.f,0.f,0.f);
        #pragma unroll
        for (int r = 0; r < 8; r++) {
            float4* arow = (float4*)(abase + ((size_t)(warp*8 + r) << 12));
            for (int g = lane; g < lo; g += 32)       __stcg(arow + g, z);
            for (int g = hi + lane; g < 1024; g += 32) __stcg(arow + g, z);
        }
    }

    const int c0 = (koff < 0) ? ((-koff) >> 6) : 0;
    int c1 = (Sdim - CK - koff) >> 6; if (c1 > 9) c1 = 9;   // chunks fully in-range

    // GEMM1 mapping: warp grid 4q x 2k; warp tile 16q x 32k; lane tile 4q x 4k
    const int g1q = ((warp & 3) << 4) + ((lane >> 3) << 2);
    const int g1k = ((warp >> 2) << 5) + ((lane & 7) << 2);

    // K-stage thread-constant indices (quad mapping, conflict-free STS)
    const int dglK = lane & 3;                          // dg = dglK + 4i
    const int kkK  = ((lane >> 2) & 7) | (warp << 3);   // 0..63, constant
    const int colK = kkK ^ (dglK << 3);                 // swizzled column

    __syncthreads();    // Qs ready

    // ======== GEMM1: raw masked scores -> attn band (GMEM/L2) ========
    {
        float4 kreg[4];
        {
            int kc = koff + (c0 << 6);
            #pragma unroll
            for (int i = 0; i < 4; i++)
                kreg[i] = K4[(size_t)(kc + kkK)*16 + dglK + 4*i];
        }
        for (int c = c0; c <= c1; c++) {
            __syncthreads();                    // prior KV readers done
            #pragma unroll
            for (int i = 0; i < 4; i++) {       // K -> transposed swizzled [d][KSTR]
                int rb = 4*dglK + 16*i;
                KV[(rb+0)*KSTR + colK] = kreg[i].x;
                KV[(rb+1)*KSTR + colK] = kreg[i].y;
                KV[(rb+2)*KSTR + colK] = kreg[i].z;
                KV[(rb+3)*KSTR + colK] = kreg[i].w;
            }
            __syncthreads();
            if (c < c1) {                       // prefetch next chunk
                int kc = koff + ((c+1) << 6);
                #pragma unroll
                for (int i = 0; i < 4; i++)
                    kreg[i] = K4[(size_t)(kc + kkK)*16 + dglK + 4*i];
            }
            u64 acc[4][2];
            #pragma unroll
            for (int j = 0; j < 4; j++) { acc[j][0] = 0ULL; acc[j][1] = 0ULL; }
            #pragma unroll 8
            for (int d = 0; d < 64; d++) {
                float4 qv = *(const float4*)(Qs + (d << 6) + g1q);
                ulonglong2 kv = *(const ulonglong2*)
                    (KV + d*KSTR + (g1k ^ (((d >> 2) & 3) << 3)));
                u64 a;
                a = pk2(qv.x); fma2(acc[0][0], a, kv.x); fma2(acc[0][1], a, kv.y);
                a = pk2(qv.y); fma2(acc[1][0], a, kv.x); fma2(acc[1][1], a, kv.y);
                a = pk2(qv.z); fma2(acc[2][0], a, kv.x); fma2(acc[2][1], a, kv.y);
                a = pk2(qv.w); fma2(acc[3][0], a, kv.x); fma2(acc[3][1], a, kv.y);
            }
            const int kg0 = koff + (c << 6) + g1k;      // in [0,4096) guaranteed
            #pragma unroll
            for (int j = 0; j < 4; j++) {
                int qg = qb + g1q + j;
                float2 a0 = upk2(acc[j][0]), a1 = upk2(acc[j][1]);
                float4 r;
                r.x = ((unsigned)(kg0+0 - qg + WIN) <= 2u*WIN) ? a0.x : -1e9f;
                r.y = ((unsigned)(kg0+1 - qg + WIN) <= 2u*WIN) ? a0.y : -1e9f;
                r.z = ((unsigned)(kg0+2 - qg + WIN) <= 2u*WIN) ? a1.x : -1e9f;
                r.w = ((unsigned)(kg0+3 - qg + WIN) <= 2u*WIN) ? a1.y : -1e9f;
                __stcg((float4*)(abase + ((size_t)(g1q+j) << 12) + kg0), r);
            }
        }
    }
    __syncthreads();    // all raw scores visible

    // ======== softmax in-place on attn band: warp owns rows 8w..8w+7 ========
    #pragma unroll 2
    for (int r = 0; r < 8; r++) {
        const int q = warp*8 + r;
        float4* row4 = (float4*)(abase + ((size_t)q << 12));
        float4 vals[5];
        float m = -3.0e38f;
        #pragma unroll
        for (int it = 0; it < 5; it++) {
            int g = goff + it*32 + lane;
            float4 v = ((unsigned)g < 1024u) ? __ldcg(row4 + g)
                                             : make_float4(-1e9f,-1e9f,-1e9f,-1e9f);
            vals[it] = v;
            m = fmaxf(m, fmaxf(fmaxf(v.x, v.y), fmaxf(v.z, v.w)));
        }
        #pragma unroll
        for (int o = 16; o > 0; o >>= 1) m = fmaxf(m, __shfl_xor_sync(~0u, m, o));
        float s = 0.f;
        #pragma unroll
        for (int it = 0; it < 5; it++) {
            float4 v = vals[it];
            v.x = __expf(v.x - m); v.y = __expf(v.y - m);
            v.z = __expf(v.z - m); v.w = __expf(v.w - m);
            s += (v.x + v.y) + (v.z + v.w);
            vals[it] = v;
        }
        #pragma unroll
        for (int o = 16; o > 0; o >>= 1) s += __shfl_xor_sync(~0u, s, o);
        float iv = 1.0f / s;
        #pragma unroll
        for (int it = 0; it < 5; it++) {
            int g = goff + it*32 + lane;
            if ((unsigned)g < 1024u) {
                float4 v = vals[it];
                __stcg(row4 + g, make_float4(v.x*iv, v.y*iv, v.z*iv, v.w*iv));
            }
        }
    }
    __syncthreads();    // FIX: all P rows normalized before any thread prefetches them

    // ======== GEMM2: out = P_norm * V, k-split-2 across thread halves ========
    const int ksp = tid >> 7;
    const int t   = tid & 127;
    const int q0  = (t >> 3) << 2;      // 0..60
    const int d0  = (t & 7) << 3;       // 0..56  (8 dims per thread)
    const int dgv = tid & 15;
    const int kv0 = tid >> 4;           // + 16i

    u64 acc2[4][4];
    #pragma unroll
    for (int j = 0; j < 4; j++)
        #pragma unroll
        for (int i = 0; i < 4; i++) acc2[j][i] = 0ULL;

    {
        float4 vreg[4], preg[4];
        {
            int kc = koff + (c0 << 6);
            #pragma unroll
            for (int i = 0; i < 4; i++) {
                vreg[i] = V4[(size_t)(kc + kv0 + 16*i)*16 + dgv];
                preg[i] = __ldcg((const float4*)(abase + ((size_t)(kv0 + 16*i) << 12))
                                 + (kc >> 2) + dgv);
            }
        }
        for (int c = c0; c <= c1; c++) {
            __syncthreads();
            #pragma unroll
            for (int i = 0; i < 4; i++) {
                *(float4*)(KV  + (kv0 + 16*i)*VSTR + 4*dgv) = vreg[i];
                *(float4*)(Pst + (kv0 + 16*i)*PSTR + 4*dgv) = preg[i];
            }
            __syncthreads();
            if (c < c1) {
                int kc = koff + ((c+1) << 6);
                #pragma unroll
                for (int i = 0; i < 4; i++) {
                    vreg[i] = V4[(size_t)(kc + kv0 + 16*i)*16 + dgv];
                    preg[i] = __ldcg((const float4*)(abase + ((size_t)(kv0 + 16*i) << 12))
                                     + (kc >> 2) + dgv);
                }
            }
            const int kb0 = ksp << 5;
            #pragma unroll 2
            for (int kb = kb0; kb < kb0 + 32; kb += 4) {
                float4 p0 = *(const float4*)(Pst + (q0+0)*PSTR + kb);
                float4 p1 = *(const float4*)(Pst + (q0+1)*PSTR + kb);
                float4 p2 = *(const float4*)(Pst + (q0+2)*PSTR + kb);
                float4 p3 = *(const float4*)(Pst + (q0+3)*PSTR + kb);
                const float* pf0 = &p0.x; const float* pf1 = &p1.x;
                const float* pf2 = &p2.x; const float* pf3 = &p3.x;
                #pragma unroll
                for (int i = 0; i < 4; i++) {
                    ulonglong2 va = *(const ulonglong2*)(KV + (kb+i)*VSTR + d0);
                    ulonglong2 vb = *(const ulonglong2*)(KV + (kb+i)*VSTR + d0 + 4);
                    u64 a;
                    a = pk2(pf0[i]); fma2(acc2[0][0],a,va.x); fma2(acc2[0][1],a,va.y);
                                     fma2(acc2[0][2],a,vb.x); fma2(acc2[0][3],a,vb.y);
                    a = pk2(pf1[i]); fma2(acc2[1][0],a,va.x); fma2(acc2[1][1],a,va.y);
                                     fma2(acc2[1][2],a,vb.x); fma2(acc2[1][3],a,vb.y);
                    a = pk2(pf2[i]); fma2(acc2[2][0],a,va.x); fma2(acc2[2][1],a,va.y);
                                     fma2(acc2[2][2],a,vb.x); fma2(acc2[2][3],a,vb.y);
                    a = pk2(pf3[i]); fma2(acc2[3][0],a,va.x); fma2(acc2[3][1],a,va.y);
                                     fma2(acc2[3][2],a,vb.x); fma2(acc2[3][3],a,vb.y);
                }
            }
        }
    }

    // ======== cross-half reduction (smem, Qs region dead) + output ========
    __syncthreads();
    float* red = Qs;                    // 4096 floats = 64x64 tile
    if (ksp == 1) {
        #pragma unroll
        for (int j = 0; j < 4; j++) {
            float2 f0 = upk2(acc2[j][0]), f1 = upk2(acc2[j][1]);
            float2 f2 = upk2(acc2[j][2]), f3 = upk2(acc2[j][3]);
            *(float4*)(red + (q0+j)*64 + d0)     = make_float4(f0.x,f0.y,f1.x,f1.y);
            *(float4*)(red + (q0+j)*64 + d0 + 4) = make_float4(f2.x,f2.y,f3.x,f3.y);
        }
    }
    __syncthreads();
    if (ksp == 0) {
        float* obase = outp + (size_t)(h*Sdim + qb)*64;
        #pragma unroll
        for (int j = 0; j < 4; j++) {
            float2 f0 = upk2(acc2[j][0]), f1 = upk2(acc2[j][1]);
            float2 f2 = upk2(acc2[j][2]), f3 = upk2(acc2[j][3]);
            float4 oA = *(const float4*)(red + (q0+j)*64 + d0);
            float4 oB = *(const float4*)(red + (q0+j)*64 + d0 + 4);
            oA.x += f0.x; oA.y += f0.y; oA.z += f1.x; oA.w += f1.y;
            oB.x += f2.x; oB.y += f2.y; oB.z += f3.x; oB.w += f3.y;
            __stcs((float4*)(obase + (size_t)(q0+j)*64 + d0),     oA);
            __stcs((float4*)(obase + (size_t)(q0+j)*64 + d0 + 4), oB);
        }
    }
}

extern "C" void kernel_launch(void* const* d_in, const int* in_sizes, int n_in,
                              void* d_out, int out_size) {
    const float* Q = (const float*)d_in[0];
    const float* K = (const float*)d_in[1];
    const float* V = (const float*)d_in[2];
    float* outp = (float*)d_out;
    float* attn = outp + (size_t)Hn*Sdim*64;        // tuple: (out, attn)

    const int smem_bytes = SMEM_FLOATS * (int)sizeof(float);    // 51200
    cudaFuncSetAttribute(swa_kernel, cudaFuncAttributeMaxDynamicSharedMemorySize,
                         smem_bytes);
    dim3 grid(Sdim / TQ, Hn);                        // (64, 16)
    swa_kernel<<<grid, NT, smem_bytes>>>(Q, K, V, outp, attn);
}

// round 16
// speedup vs baseline: 1.0963x; 1.0963x over previous
#include <cuda_runtime.h>

#define Sdim 4096
#define WIN  256
#define Hn   16
#define TQ   32
#define NT   256

#define SM_KV 18432                 /* PT[576][32] before it */
#define SM_QS 26624
#define SMEM_FLOATS 28672           /* 114688 B = 112 KB exactly */

typedef unsigned long long u64;

__device__ __forceinline__ u64 pk2(float v) {
    u64 r; asm("mov.b64 %0,{%1,%1};" : "=l"(r) : "f"(v)); return r;
}
__device__ __forceinline__ void fma2(u64 &d, u64 a, u64 b) {
    asm("fma.rn.f32x2 %0,%1,%2,%0;" : "+l"(d) : "l"(a), "l"(b));
}
__device__ __forceinline__ float2 upk2(u64 v) {
    float2 f; asm("mov.b64 {%0,%1},%2;" : "=f"(f.x), "=f"(f.y) : "l"(v)); return f;
}

__global__ __launch_bounds__(NT, 2)
void swa_kernel(const float* __restrict__ Q, const float* __restrict__ K,
                const float* __restrict__ V, float* __restrict__ outp,
                float* __restrict__ attn)
{
    extern __shared__ float sm[];
    float* PT = sm;                 // P^T [576 k][32 q] XOR-swizzled, rows 128B
    float* KV = sm + SM_KV;         // G1: K^T[64d][128k] swz ; G2: V[128k][64d] swz
    float* Qs = sm + SM_QS;         // Q^T [64d][32q] swz, *0.125 ; later: red buffer

    const int h    = blockIdx.y;
    const int qb   = blockIdx.x * TQ;
    const int tid  = threadIdx.x;
    const int warp = tid >> 5, lane = tid & 31;
    const int koff = qb - WIN;      // band buffer keys [koff, koff+576)
    const int goff = koff >> 2;
    float* abase = attn + (size_t)(h*Sdim + qb)*Sdim;

    const float4* Q4 = (const float4*)(Q + (size_t)(h*Sdim + qb)*64);
    const float4* K4 = (const float4*)(K + (size_t)h*Sdim*64);
    const float4* V4 = (const float4*)(V + (size_t)h*Sdim*64);

    // ---- Q load + transpose (swizzled), fold in 1/8 ----
    {
        int q = tid >> 3;
        #pragma unroll
        for (int i = 0; i < 2; i++) {
            int dg = (tid & 7) + 8*i;
            float4 v = Q4[q*16 + dg];
            float vv[4] = {v.x, v.y, v.z, v.w};
            #pragma unroll
            for (int j = 0; j < 4; j++) {
                int d = 4*dg + j;
                Qs[(d<<5) + ((((q>>2) ^ (d&7))<<2) | (q&3))] = vv[j]*0.125f;
            }
        }
    }
    // ---- PT prefill -1e9 ----
    {
        float4 mn = make_float4(-1e9f,-1e9f,-1e9f,-1e9f);
        #pragma unroll
        for (int i = 0; i < 18; i++)
            *(float4*)(PT + ((i*NT + tid)<<2)) = mn;
    }
    // ---- zero-fill attn outside band: warp owns rows 4w..4w+3 ----
    {
        int lo = goff > 0 ? goff : 0;
        int hi = goff + 144 < 1024 ? goff + 144 : 1024;
        const float4 z = make_float4(0.f,0.f,0.f,0.f);
        #pragma unroll
        for (int r = 0; r < 4; r++) {
            float4* arow = (float4*)(abase + ((size_t)(4*warp + r) << 12));
            for (int g = lane; g < lo; g += 32)        __stcs(arow + g, z);
            for (int g = hi + lane; g < 1024; g += 32) __stcs(arow + g, z);
        }
    }

    const int lv0 = koff < 0 ? -koff : 0;
    const int lv1 = (4096 - koff < 576) ? 4096 - koff : 576;
    const int s_lo = lv0 >> 7, s_hi = (lv1 - 1) >> 7;

    const int q0   = (lane >> 2) << 2;      // 8 q-groups
    const int kq   = lane & 3;              // k-group / dgl reuse
    const int dglK = lane & 3;
    const int kkK  = ((lane >> 2) & 7) | (warp << 3);   // 0..63

    __syncthreads();

    // ======== GEMM1: P^T raw masked scores into PT ========
    {
        float4 kreg[8];
        {
            int kgb = koff + (s_lo << 7);
            #pragma unroll
            for (int i = 0; i < 8; i++) {
                int key = kkK + ((i>>2)<<6), dg = dglK + ((i&3)<<2);
                int kg = kgb + key;
                kreg[i] = ((unsigned)kg < 4096u) ? K4[(size_t)kg*16 + dg]
                                                 : make_float4(0.f,0.f,0.f,0.f);
            }
        }
        for (int s = s_lo; s <= s_hi; s++) {
            __syncthreads();
            #pragma unroll
            for (int i = 0; i < 8; i++) {       // K -> K^T swizzled
                int key = kkK + ((i>>2)<<6), dg = dglK + ((i&3)<<2);
                int g = key >> 2, r = key & 3;
                float vv[4] = {kreg[i].x, kreg[i].y, kreg[i].z, kreg[i].w};
                #pragma unroll
                for (int j = 0; j < 4; j++) {
                    int d = 4*dg + j;
                    KV[(d<<7) + (((g ^ (d&7))<<2) | r)] = vv[j];
                }
            }
            __syncthreads();
            if (s < s_hi) {
                int kgb = koff + ((s+1) << 7);
                #pragma unroll
                for (int i = 0; i < 8; i++) {
                    int key = kkK + ((i>>2)<<6), dg = dglK + ((i&3)<<2);
                    int kg = kgb + key;
                    kreg[i] = ((unsigned)kg < 4096u) ? K4[(size_t)kg*16 + dg]
                                                     : make_float4(0.f,0.f,0.f,0.f);
                }
            }
            u64 acc[4][2];
            #pragma unroll
            for (int j = 0; j < 4; j++) { acc[j][0] = 0ULL; acc[j][1] = 0ULL; }
            const int gk = (warp << 2) + kq;        // f4-group of this lane's keys
            #pragma unroll 8
            for (int d = 0; d < 64; d++) {
                float4 qv = *(const float4*)(Qs + (d<<5) + (q0 ^ ((d&7)<<2)));
                ulonglong2 kv = *(const ulonglong2*)(KV + (d<<7) + ((gk ^ (d&7))<<2));
                u64 a;
                a = pk2(qv.x); fma2(acc[0][0],a,kv.x); fma2(acc[0][1],a,kv.y);
                a = pk2(qv.y); fma2(acc[1][0],a,kv.x); fma2(acc[1][1],a,kv.y);
                a = pk2(qv.z); fma2(acc[2][0],a,kv.x); fma2(acc[2][1],a,kv.y);
                a = pk2(qv.w); fma2(acc[3][0],a,kv.x); fma2(acc[3][1],a,kv.y);
            }
            float av[4][4];
            #pragma unroll
            for (int j = 0; j < 4; j++) {
                float2 f0 = upk2(acc[j][0]), f1 = upk2(acc[j][1]);
                av[j][0] = f0.x; av[j][1] = f0.y; av[j][2] = f1.x; av[j][3] = f1.y;
            }
            const int lkb = (s<<7) + (warp<<4) + (kq<<2);
            #pragma unroll
            for (int kk = 0; kk < 4; kk++) {
                int lk = lkb + kk;
                int kg = koff + lk;
                if (lk < 576 && (unsigned)kg < 4096u) {
                    float r4[4];
                    #pragma unroll
                    for (int j = 0; j < 4; j++) {
                        int qg = qb + q0 + j;
                        r4[j] = ((unsigned)(kg - qg + WIN) <= 2u*WIN) ? av[j][kk] : -1e9f;
                    }
                    *(float4*)(PT + (lk<<5) + (q0 ^ (((lk>>2)&7)<<2))) =
                        make_float4(r4[0], r4[1], r4[2], r4[3]);
                }
            }
        }
    }
    __syncthreads();

    // ======== softmax on PT columns, normalize in place, write attn band ====
    {
        const int qq = warp << 2;       // rows qq..qq+3
        float m0=-3.0e38f, m1=-3.0e38f, m2=-3.0e38f, m3=-3.0e38f;
        #pragma unroll
        for (int it = 0; it < 18; it++) {
            int k = (it<<5) + lane;
            float4 v = *(const float4*)(PT + (k<<5) + (qq ^ (((k>>2)&7)<<2)));
            m0 = fmaxf(m0, v.x); m1 = fmaxf(m1, v.y);
            m2 = fmaxf(m2, v.z); m3 = fmaxf(m3, v.w);
        }
        #pragma unroll
        for (int o = 16; o > 0; o >>= 1) {
            m0 = fmaxf(m0, __shfl_xor_sync(~0u, m0, o));
            m1 = fmaxf(m1, __shfl_xor_sync(~0u, m1, o));
            m2 = fmaxf(m2, __shfl_xor_sync(~0u, m2, o));
            m3 = fmaxf(m3, __shfl_xor_sync(~0u, m3, o));
        }
        float s0=0.f, s1=0.f, s2=0.f, s3=0.f;
        #pragma unroll
        for (int it = 0; it < 18; it++) {
            int k = (it<<5) + lane;
            float* p = PT + (k<<5) + (qq ^ (((k>>2)&7)<<2));
            float4 v = *(const float4*)p;
            v.x = __expf(v.x - m0); v.y = __expf(v.y - m1);
            v.z = __expf(v.z - m2); v.w = __expf(v.w - m3);
            s0 += v.x; s1 += v.y; s2 += v.z; s3 += v.w;
            *(float4*)p = v;
        }
        #pragma unroll
        for (int o = 16; o > 0; o >>= 1) {
            s0 += __shfl_xor_sync(~0u, s0, o);
            s1 += __shfl_xor_sync(~0u, s1, o);
            s2 += __shfl_xor_sync(~0u, s2, o);
            s3 += __shfl_xor_sync(~0u, s3, o);
        }
        float i0 = 1.0f/s0, i1 = 1.0f/s1, i2 = 1.0f/s2, i3 = 1.0f/s3;
        #pragma unroll
        for (int it = 0; it < 18; it++) {
            int k = (it<<5) + lane;
            float* p = PT + (k<<5) + (qq ^ (((k>>2)&7)<<2));
            float4 v = *(const float4*)p;
            v.x *= i0; v.y *= i1; v.z *= i2; v.w *= i3;
            *(float4*)p = v;                    // P now fully normalized
            int kg = koff + k;
            if ((unsigned)kg < 4096u) {
                __stcs(abase + ((size_t)(qq+0)<<12) + kg, v.x);
                __stcs(abase + ((size_t)(qq+1)<<12) + kg, v.y);
                __stcs(abase + ((size_t)(qq+2)<<12) + kg, v.z);
                __stcs(abase + ((size_t)(qq+3)<<12) + kg, v.w);
            }
        }
    }
    __syncthreads();

    // ======== GEMM2: out = P_norm^T-consumed * V ========
    const int d0    = ((warp & 3) << 4) + (kq << 2);    // 0..60
    const int dg0   = d0 >> 2;
    const int khalf = warp >> 2;

    u64 acc2[4][2];
    #pragma unroll
    for (int j = 0; j < 4; j++) { acc2[j][0] = 0ULL; acc2[j][1] = 0ULL; }

    {
        float4 vreg[8];
        {
            int kgb = koff + (s_lo << 7);
            #pragma unroll
            for (int i = 0; i < 8; i++) {
                int key = kkK + ((i>>2)<<6), dg = dglK + ((i&3)<<2);
                int kg = kgb + key;
                vreg[i] = ((unsigned)kg < 4096u) ? V4[(size_t)kg*16 + dg]
                                                 : make_float4(0.f,0.f,0.f,0.f);
            }
        }
        for (int s = s_lo; s <= s_hi; s++) {
            __syncthreads();
            #pragma unroll
            for (int i = 0; i < 8; i++) {       // V[k][64d] swizzled
                int key = kkK + ((i>>2)<<6), dg = dglK + ((i&3)<<2);
                *(float4*)(KV + (key<<6) + ((dg ^ (key&7))<<2)) = vreg[i];
            }
            __syncthreads();
            if (s < s_hi) {
                int kgb = koff + ((s+1) << 7);
                #pragma unroll
                for (int i = 0; i < 8; i++) {
                    int key = kkK + ((i>>2)<<6), dg = dglK + ((i&3)<<2);
                    int kg = kgb + key;
                    vreg[i] = ((unsigned)kg < 4096u) ? V4[(size_t)kg*16 + dg]
                                                     : make_float4(0.f,0.f,0.f,0.f);
                }
            }
            int kmax = 576 - (s<<7); if (kmax > 128) kmax = 128;
            int khn  = kmax >> 1;
            int kbeg = khalf * khn;
            #pragma unroll 8
            for (int k = kbeg; k < kbeg + khn; k++) {
                int lk = (s<<7) + k;
                float4 p = *(const float4*)(PT + (lk<<5) + (q0 ^ (((lk>>2)&7)<<2)));
                ulonglong2 vv = *(const ulonglong2*)(KV + (k<<6) + ((dg0 ^ (k&7))<<2));
                u64 a;
                a = pk2(p.x); fma2(acc2[0][0],a,vv.x); fma2(acc2[0][1],a,vv.y);
                a = pk2(p.y); fma2(acc2[1][0],a,vv.x); fma2(acc2[1][1],a,vv.y);
                a = pk2(p.z); fma2(acc2[2][0],a,vv.x); fma2(acc2[2][1],a,vv.y);
                a = pk2(p.w); fma2(acc2[3][0],a,vv.x); fma2(acc2[3][1],a,vv.y);
            }
        }
    }

    // ======== cross-half reduction (Qs region dead) + output ========
    __syncthreads();
    float* red = Qs;                    // 2048 floats = 32q x 64d
    if (khalf == 1) {
        #pragma unroll
        for (int j = 0; j < 4; j++) {
            float2 f0 = upk2(acc2[j][0]), f1 = upk2(acc2[j][1]);
            *(float4*)(red + ((q0+j)<<6) + d0) = make_float4(f0.x, f0.y, f1.x, f1.y);
        }
    }
    __syncthreads();
    if (khalf == 0) {
        float* obase = outp + (size_t)(h*Sdim + qb)*64;
        #pragma unroll
        for (int j = 0; j < 4; j++) {
            float2 f0 = upk2(acc2[j][0]), f1 = upk2(acc2[j][1]);
            float4 o = *(const float4*)(red + ((q0+j)<<6) + d0);
            o.x += f0.x; o.y += f0.y; o.z += f1.x; o.w += f1.y;
            __stcs((float4*)(obase + (size_t)(q0+j)*64 + d0), o);
        }
    }
}

extern "C" void kernel_launch(void* const* d_in, const int* in_sizes, int n_in,
                              void* d_out, int out_size) {
    const float* Q = (const float*)d_in[0];
    const float* K = (const float*)d_in[1];
    const float* V = (const float*)d_in[2];
    float* outp = (float*)d_out;
    float* attn = outp + (size_t)Hn*Sdim*64;        // tuple: (out, attn)

    const int smem_bytes = SMEM_FLOATS * (int)sizeof(float);    // 114688
    cudaFuncSetAttribute(swa_kernel, cudaFuncAttributeMaxDynamicSharedMemorySize,
                         smem_bytes);
    dim3 grid(Sdim / TQ, Hn);                        // (128, 16)
    swa_kernel<<<grid, NT, smem_bytes>>>(Q, K, V, outp, attn);
}

// round 17
// speedup vs baseline: 1.3851x; 1.2635x over previous
#include <cuda_runtime.h>

#define Sdim 4096
#define Ddim 64
#define WIN  256
#define Hn   16
#define TQ   32
#define CK   64
#define NCH  9
#define KBUF 576
#define SROW 580
#define NT   256
#define KSTR 66
#define VSTR 68

#define SM_QS   (TQ*SROW)              /* 18560 */
#define SM_KV   (SM_QS + 2048)         /* 20608 */
#define SM_INV  (SM_KV + CK*VSTR)      /* 24960 */
#define SM_PART (SM_INV + 32)          /* 24992 */
#define SMEM_FLOATS (SM_PART + 128)    /* 25120 floats = 100480 B */

typedef unsigned long long u64;

__device__ __forceinline__ u64 pk2(float v) {
    u64 r; asm("mov.b64 %0,{%1,%1};" : "=l"(r) : "f"(v)); return r;
}
__device__ __forceinline__ void fma2(u64 &d, u64 a, u64 b) {
    asm("fma.rn.f32x2 %0,%1,%2,%0;" : "+l"(d) : "l"(a), "l"(b));
}
__device__ __forceinline__ float2 upk2(u64 v) {
    float2 f; asm("mov.b64 {%0,%1},%2;" : "=f"(f.x), "=f"(f.y) : "l"(v)); return f;
}

__global__ __launch_bounds__(NT, 2)
void swa_kernel(const float* __restrict__ Q, const float* __restrict__ K,
                const float* __restrict__ V, float* __restrict__ outp,
                float* __restrict__ attn)
{
    extern __shared__ float sm[];
    float* scores = sm;                 // [32][SROW]  holds p = exp(masked s)
    float* Qs     = sm + SM_QS;         // [64][32] d-major, pre-scaled 0.125
    float* KV     = sm + SM_KV;         // K: [d][KSTR] / V: [k][VSTR]
    float* invs   = sm + SM_INV;        // [32]
    float* part   = sm + SM_PART;       // [4][32] row-sum partials

    const int h    = blockIdx.y;
    const int qb   = blockIdx.x * TQ;
    const int tid  = threadIdx.x;
    const int koff = qb - WIN;          // buffer keys [koff, koff+576)
    const int goff = koff >> 2;
    float* abase   = attn + (size_t)(h*Sdim + qb)*Sdim;
    const int warp = tid >> 5, lane = tid & 31;

    const float4* Q4 = (const float4*)(Q + (size_t)(h*Sdim + qb)*Ddim);
    const float4* K4 = (const float4*)(K + (size_t)h*Sdim*Ddim);
    const float4* V4 = (const float4*)(V + (size_t)h*Sdim*Ddim);
    const float4 fzero = make_float4(0.f,0.f,0.f,0.f);

    // ---- Q load + transpose (warp w -> d cols 8w..8w+7), conflict-free STS ----
    {
        float4 a = Q4[lane*16 + warp*2];
        float4 b = Q4[lane*16 + warp*2 + 1];
        int d0 = warp*8;
        Qs[(d0+0)*32 + lane] = a.x*0.125f;
        Qs[(d0+1)*32 + lane] = a.y*0.125f;
        Qs[(d0+2)*32 + lane] = a.z*0.125f;
        Qs[(d0+3)*32 + lane] = a.w*0.125f;
        Qs[(d0+4)*32 + lane] = b.x*0.125f;
        Qs[(d0+5)*32 + lane] = b.y*0.125f;
        Qs[(d0+6)*32 + lane] = b.z*0.125f;
        Qs[(d0+7)*32 + lane] = b.w*0.125f;
    }

    // ---- zero-fill attn outside band: warp w owns rows 4w..4w+3 ----
    {
        int lo = max(0, goff), hi = min(1024, goff + KBUF/4);
        #pragma unroll
        for (int r = 0; r < 4; r++) {
            float4* arow = (float4*)(abase + ((size_t)(warp*4 + r) << 12));
            for (int g = lane; g < lo; g += 32) __stcs(arow + g, fzero);
            for (int g = hi + lane; g < 1024; g += 32) __stcs(arow + g, fzero);
        }
    }

    const int c0 = (koff < 0) ? ((-koff) >> 6) : 0;
    const int c1 = min(NCH-1, (Sdim-1-koff) >> 6);

    // GEMM1 mapping: warp grid 2q x 4k; warp tile 16q x 16k; lane tile 4q x 2k
    const int g1q = ((warp & 1) << 4) + ((lane >> 3) << 2);
    const int g1k = ((warp >> 1) << 4) + ((lane & 7) << 1);

    // K-stage quad mapping (conflict-free STS): thread owns key kkK, dg = dglK+4i
    const int dglK = lane & 3;
    const int kkK  = ((lane >> 2) & 7) | (warp << 3);   // 0..63

    // fill scores of invalid chunks with 0 (p = exp contribution of masked = 0)
    for (int c = 0; c < c0; c++) {
        #pragma unroll
        for (int j = 0; j < 4; j++)
            *(float2*)&scores[(g1q+j)*SROW + c*CK + g1k] = make_float2(0.f,0.f);
    }
    for (int c = c1+1; c < NCH; c++) {
        #pragma unroll
        for (int j = 0; j < 4; j++)
            *(float2*)&scores[(g1q+j)*SROW + c*CK + g1k] = make_float2(0.f,0.f);
    }
    __syncthreads();   // Qs ready

    float rsum[4] = {0.f, 0.f, 0.f, 0.f};   // per-lane row-sum partials

    // ======== GEMM1 + fused exp: p -> scores, register K-prefetch ========
    {
        float4 kreg[4];
        {   // prefetch chunk c0 (thread's key kkK, 4 dg quads)
            int kg = koff + c0*CK + kkK;
            bool ok = (unsigned)kg < Sdim;
            #pragma unroll
            for (int i = 0; i < 4; i++)
                kreg[i] = ok ? K4[(size_t)kg*16 + dglK + 4*i] : fzero;
        }
        for (int c = c0; c <= c1; c++) {
            __syncthreads();            // KV free
            #pragma unroll
            for (int i = 0; i < 4; i++) {   // conflict-free STS transpose
                int rb = 4*dglK + 16*i;
                KV[(rb+0)*KSTR + kkK] = kreg[i].x;
                KV[(rb+1)*KSTR + kkK] = kreg[i].y;
                KV[(rb+2)*KSTR + kkK] = kreg[i].z;
                KV[(rb+3)*KSTR + kkK] = kreg[i].w;
            }
            __syncthreads();
            if (c < c1) {               // prefetch next chunk
                int kg = koff + (c+1)*CK + kkK;
                bool ok = (unsigned)kg < Sdim;
                #pragma unroll
                for (int i = 0; i < 4; i++)
                    kreg[i] = ok ? K4[(size_t)kg*16 + dglK + 4*i] : fzero;
            }
            u64 acc[4] = {0ULL,0ULL,0ULL,0ULL};
            #pragma unroll 16
            for (int d = 0; d < Ddim; d++) {
                float4 qv = *(const float4*)(Qs + d*32 + g1q);
                u64 kv = *(const u64*)(KV + d*KSTR + g1k);
                fma2(acc[0], pk2(qv.x), kv);
                fma2(acc[1], pk2(qv.y), kv);
                fma2(acc[2], pk2(qv.z), kv);
                fma2(acc[3], pk2(qv.w), kv);
            }
            const int kg0 = koff + c*CK + g1k;
            #pragma unroll
            for (int j = 0; j < 4; j++) {
                int qg = qb + g1q + j;
                float2 a = upk2(acc[j]);
                float px = ((unsigned)kg0     < Sdim && (unsigned)(kg0   - qg + WIN) <= 2u*WIN)
                           ? __expf(a.x) : 0.f;
                float py = ((unsigned)(kg0+1) < Sdim && (unsigned)(kg0+1 - qg + WIN) <= 2u*WIN)
                           ? __expf(a.y) : 0.f;
                rsum[j] += px + py;
                *(float2*)&scores[(g1q+j)*SROW + c*CK + g1k] = make_float2(px, py);
            }
        }
    }

    // ---- row-sum reduction: shuffle over k-octet, partials over 4 k-warps ----
    #pragma unroll
    for (int o = 1; o <= 4; o <<= 1) {
        rsum[0] += __shfl_xor_sync(~0u, rsum[0], o);
        rsum[1] += __shfl_xor_sync(~0u, rsum[1], o);
        rsum[2] += __shfl_xor_sync(~0u, rsum[2], o);
        rsum[3] += __shfl_xor_sync(~0u, rsum[3], o);
    }
    if ((lane & 7) == 0) {
        int q = g1q;                    // rows q..q+3 complete within this warp
        #pragma unroll
        for (int j = 0; j < 4; j++)
            part[(warp >> 1)*32 + q + j] = rsum[j];
    }
    __syncthreads();
    if (tid < 32) {
        float s = part[tid] + part[32 + tid] + part[64 + tid] + part[96 + tid];
        invs[tid] = 1.0f / s;
    }
    __syncthreads();

    // ======== band attn write: warp w owns rows 4w..4w+3 ========
    #pragma unroll
    for (int r = 0; r < 4; r++) {
        const int q = warp*4 + r;
        const float iv = invs[q];
        const float* row = scores + q*SROW;
        float* arow = abase + ((size_t)q << 12);
        #pragma unroll
        for (int it = 0; it < 5; it++) {
            int bg = it*32 + lane;
            int g  = bg + goff;
            if (bg < 144 && (unsigned)g < 1024u) {
                float4 p = *(const float4*)(row + (bg << 2));
                __stcs((float4*)(arow + (g << 2)),
                       make_float4(p.x*iv, p.y*iv, p.z*iv, p.w*iv));
            }
        }
    }

    // ======== GEMM2: out = P V, k-split-2, register V-prefetch ========
    const int ksp = tid >> 7;
    const int t   = tid & 127;
    const int q0  = (t >> 4) << 2;      // 0..28
    const int d0  = (t & 15) << 2;      // 0..60

    u64 acc2[4][2];
    #pragma unroll
    for (int j = 0; j < 4; j++) { acc2[j][0] = 0ULL; acc2[j][1] = 0ULL; }

    {
        float4 vreg[4];
        {   // prefetch chunk c0
            int kc = koff + c0*CK;
            #pragma unroll
            for (int i = 0; i < 4; i++) {
                int idx = tid + NT*i;
                int kg = kc + (idx >> 4);
                vreg[i] = ((unsigned)kg < Sdim) ? V4[(size_t)kg*16 + (idx & 15)] : fzero;
            }
        }
        for (int c = c0; c <= c1; c++) {
            __syncthreads();            // prev KV readers done
            #pragma unroll
            for (int i = 0; i < 4; i++) {
                int idx = tid + NT*i;
                int kk = idx >> 4, dg = idx & 15;
                *(float4*)&KV[kk*VSTR + 4*dg] = vreg[i];
            }
            __syncthreads();
            if (c < c1) {
                int kc = koff + (c+1)*CK;
                #pragma unroll
                for (int i = 0; i < 4; i++) {
                    int idx = tid + NT*i;
                    int kg = kc + (idx >> 4);
                    vreg[i] = ((unsigned)kg < Sdim) ? V4[(size_t)kg*16 + (idx & 15)] : fzero;
                }
            }
            const float* srow = scores + c*CK;
            #pragma unroll
            for (int kb = 0; kb < 32; kb += 4) {
                int kbs = ksp*32 + kb;
                float4 p0 = *(const float4*)(srow + (q0+0)*SROW + kbs);
                float4 p1 = *(const float4*)(srow + (q0+1)*SROW + kbs);
                float4 p2 = *(const float4*)(srow + (q0+2)*SROW + kbs);
                float4 p3 = *(const float4*)(srow + (q0+3)*SROW + kbs);
                #pragma unroll
                for (int i = 0; i < 4; i++) {
                    ulonglong2 vv = *(const ulonglong2*)(KV + (kbs+i)*VSTR + d0);
                    const float* f0 = &p0.x; const float* f1 = &p1.x;
                    const float* f2 = &p2.x; const float* f3 = &p3.x;
                    u64 a;
                    a = pk2(f0[i]); fma2(acc2[0][0], a, vv.x); fma2(acc2[0][1], a, vv.y);
                    a = pk2(f1[i]); fma2(acc2[1][0], a, vv.x); fma2(acc2[1][1], a, vv.y);
                    a = pk2(f2[i]); fma2(acc2[2][0], a, vv.x); fma2(acc2[2][1], a, vv.y);
                    a = pk2(f3[i]); fma2(acc2[3][0], a, vv.x); fma2(acc2[3][1], a, vv.y);
                }
            }
        }
    }

    // ======== cross-half reduction + output ========
    __syncthreads();
    float* red = sm;                    // scores dead; 2048 floats
    if (ksp == 1) {
        #pragma unroll
        for (int j = 0; j < 4; j++) {
            float2 f0 = upk2(acc2[j][0]), f1 = upk2(acc2[j][1]);
            *(float4*)&red[j*512 + t*4] = make_float4(f0.x, f0.y, f1.x, f1.y);
        }
    }
    __syncthreads();
    if (ksp == 0) {
        float* obase = outp + (size_t)(h*Sdim + qb)*Ddim;
        #pragma unroll
        for (int j = 0; j < 4; j++) {
            float2 f0 = upk2(acc2[j][0]), f1 = upk2(acc2[j][1]);
            float4 o = *(const float4*)&red[j*512 + t*4];
            float iv = invs[q0 + j];
            o.x = (o.x + f0.x) * iv;
            o.y = (o.y + f0.y) * iv;
            o.z = (o.z + f1.x) * iv;
            o.w = (o.w + f1.y) * iv;
            __stcs((float4*)(obase + (size_t)(q0 + j)*Ddim + d0), o);
        }
    }
}

extern "C" void kernel_launch(void* const* d_in, const int* in_sizes, int n_in,
                              void* d_out, int out_size) {
    const float* Q = (const float*)d_in[0];
    const float* K = (const float*)d_in[1];
    const float* V = (const float*)d_in[2];
    float* outp = (float*)d_out;
    float* attn = outp + (size_t)Hn*Sdim*Ddim;

    const int smem_bytes = SMEM_FLOATS * (int)sizeof(float);  // 100480
    cudaFuncSetAttribute(swa_kernel, cudaFuncAttributeMaxDynamicSharedMemorySize,
                         smem_bytes);
    dim3 grid(Sdim / TQ, Hn);                        // (128, 16)
    swa_kernel<<<grid, NT, smem_bytes>>>(Q, K, V, outp, attn);
}